// round 11
// baseline (speedup 1.0000x reference)
#include <cuda_runtime.h>
#include <cuda_fp16.h>
#include <stdint.h>

#define DD 128
#define NMAX 100000
#define EMAX 3200000
typedef unsigned long long u64;

// -------- device-global scratch --------
__device__ float  g_agg[(size_t)NMAX * DD];
__device__ float  g_h0 [(size_t)NMAX * DD];
__device__ float  g_h1 [(size_t)NMAX * DD];
__device__ __half g_h16[(size_t)NMAX * DD];
__device__ int    g_cnt [NMAX];
__device__ int    g_cur [NMAX];
__device__ int    g_incl[NMAX];
__device__ int    g_bsum[512];
__device__ int    g_rowptr[NMAX + 1];
__device__ int    g_csr [EMAX];

// ==================== conv16 + zero counters ====================
__global__ void conv16z_kernel(const float* __restrict__ src, __half* __restrict__ dst,
                               int* __restrict__ cnt, int* __restrict__ cur,
                               int total4, int n) {
    int i = blockIdx.x * blockDim.x + threadIdx.x;
    if (i < total4) {
        float4 v = __ldg((const float4*)src + i);
        __half2 a = __floats2half2_rn(v.x, v.y);
        __half2 b = __floats2half2_rn(v.z, v.w);
        *((uint2*)dst + i) = make_uint2(*(uint32_t*)&a, *(uint32_t*)&b);
    }
    if (i < n) { cnt[i] = 0; cur[i] = 0; }
}

// ==================== CSR build ====================
__global__ void deg_kernel(const int* __restrict__ dst, int* __restrict__ cnt, long long E) {
    long long e = (long long)blockIdx.x * blockDim.x + threadIdx.x;
    if (e < E) atomicAdd(&cnt[dst[e]], 1);
}

#define SB 256
__global__ void scan1(const int* __restrict__ cnt, int* __restrict__ incl,
                      int* __restrict__ bsum, int n) {
    __shared__ int sm[SB];
    int i = blockIdx.x * SB + threadIdx.x;
    int v = (i < n) ? cnt[i] : 0;
    sm[threadIdx.x] = v;
    __syncthreads();
    for (int off = 1; off < SB; off <<= 1) {
        int t = (threadIdx.x >= off) ? sm[threadIdx.x - off] : 0;
        __syncthreads();
        sm[threadIdx.x] += t;
        __syncthreads();
    }
    if (i < n) incl[i] = sm[threadIdx.x];
    if (threadIdx.x == SB - 1) bsum[blockIdx.x] = sm[SB - 1];
}

__global__ void scan2(int* __restrict__ bsum, int nb) {
    __shared__ int sm[512];
    int v = ((int)threadIdx.x < nb) ? bsum[threadIdx.x] : 0;
    sm[threadIdx.x] = v;
    __syncthreads();
    for (int off = 1; off < 512; off <<= 1) {
        int t = (threadIdx.x >= off) ? sm[threadIdx.x - off] : 0;
        __syncthreads();
        sm[threadIdx.x] += t;
        __syncthreads();
    }
    if ((int)threadIdx.x < nb) bsum[threadIdx.x] = sm[threadIdx.x] - v;
}

__global__ void scan3(const int* __restrict__ incl, const int* __restrict__ cnt,
                      const int* __restrict__ bsum, int* __restrict__ rowptr,
                      int n, int E) {
    int i = blockIdx.x * 256 + threadIdx.x;
    if (i < n) rowptr[i] = incl[i] - cnt[i] + bsum[i / SB];
    if (i == 0) rowptr[n] = E;
}

__global__ void place_kernel(const int* __restrict__ ei, const int* __restrict__ rowptr,
                             int* __restrict__ cur, int* __restrict__ csr, long long E) {
    long long e = (long long)blockIdx.x * blockDim.x + threadIdx.x;
    if (e < E) {
        int s = ei[e];
        int d = ei[E + e];
        int pos = rowptr[d] + atomicAdd(&cur[d], 1);
        csr[pos] = s;
    }
}

// ==================== mean aggregation (R10 form) ====================
__global__ void agg_kernel(const __half* __restrict__ h16, const int* __restrict__ rowptr,
                           const int* __restrict__ csr, float* __restrict__ agg, int n) {
    int d = blockIdx.x * (blockDim.x >> 5) + (threadIdx.x >> 5);
    int lane = threadIdx.x & 31;
    if (d >= n) return;
    int beg = __ldg(&rowptr[d]);
    int end = __ldg(&rowptr[d + 1]);
    int half = lane >> 4;
    int hl   = lane & 15;

    float acc[8];
    #pragma unroll
    for (int q = 0; q < 8; q++) acc[q] = 0.f;

    for (int j = beg; j < end; j += 32) {
        int cnt = min(32, end - j);
        int s = (lane < cnt) ? __ldg(&csr[j + lane]) : 0;
        int npair = cnt >> 1;
        #pragma unroll 4
        for (int t = 0; t < npair; t++) {
            int ss = __shfl_sync(0xffffffffu, s, 2 * t + half);
            uint4 raw = __ldg((const uint4*)(h16 + (size_t)ss * DD) + hl);
            const __half2* hp = (const __half2*)&raw;
            #pragma unroll
            for (int q = 0; q < 4; q++) {
                float2 f = __half22float2(hp[q]);
                acc[2 * q]     += f.x;
                acc[2 * q + 1] += f.y;
            }
        }
        if (cnt & 1) {
            int ss = __shfl_sync(0xffffffffu, s, cnt - 1);
            if (half == 0) {
                uint4 raw = __ldg((const uint4*)(h16 + (size_t)ss * DD) + hl);
                const __half2* hp = (const __half2*)&raw;
                #pragma unroll
                for (int q = 0; q < 4; q++) {
                    float2 f = __half22float2(hp[q]);
                    acc[2 * q]     += f.x;
                    acc[2 * q + 1] += f.y;
                }
            }
        }
    }
    #pragma unroll
    for (int q = 0; q < 8; q++) acc[q] += __shfl_xor_sync(0xffffffffu, acc[q], 16);

    if (half == 0) {
        float inv = 1.0f / fmaxf((float)(end - beg), 1.0f);
        float4 v0 = make_float4(acc[0] * inv, acc[1] * inv, acc[2] * inv, acc[3] * inv);
        float4 v1 = make_float4(acc[4] * inv, acc[5] * inv, acc[6] * inv, acc[7] * inv);
        float4* dst = (float4*)(agg + (size_t)d * DD + hl * 8);
        dst[0] = v0;
        dst[1] = v1;
    }
}

// ==================== f32x2 helpers ====================
__device__ __forceinline__ void fma2(u64& d, u64 a, u64 b) {
    asm("fma.rn.f32x2 %0, %1, %2, %0;" : "+l"(d) : "l"(a), "l"(b));
}
__device__ __forceinline__ u64 dup2(float x) {
    u64 r;
    asm("mov.b64 %0, {%1, %1};" : "=l"(r) : "r"(__float_as_uint(x)));
    return r;
}
__device__ __forceinline__ void unpk(float& lo, float& hi, u64 v) {
    unsigned a, b;
    asm("mov.b64 {%0, %1}, %2;" : "=r"(a), "=r"(b) : "l"(v));
    lo = __uint_as_float(a); hi = __uint_as_float(b);
}

// ==================== K=128 GEMM, 8x8 blocking, conflict-free ====================
// PHASE 0: out = A @ W^T + bias          (partial)
// PHASE 1: out = relu?(A @ W^T + out)    (+ optional h16 emit)
#define GEMM_SMEM ((128 * 128 + 128 * 128) * sizeof(float))   // 128KB

template<int PHASE>
__device__ __forceinline__ void gemm_body(const float* __restrict__ A,
                                          const float* __restrict__ W,
                                          const float* __restrict__ bias,
                                          float* __restrict__ out,
                                          __half* __restrict__ h16out,
                                          int n, int relu) {
    extern __shared__ float sm[];
    float* Wt = sm;                 // [128][128]
    float* As = sm + 128 * 128;     // [128][128]
    int tid = threadIdx.x;
    int row0 = blockIdx.x * 128;

    #pragma unroll
    for (int i = 0; i < 16; i++) {
        int fidx = i * 256 + tid;
        int j = fidx & 127;
        int k = (fidx >> 7) << 2;
        float4 v = __ldg((const float4*)(W + j * DD + k));
        Wt[(k + 0) * 128 + j] = v.x;
        Wt[(k + 1) * 128 + j] = v.y;
        Wt[(k + 2) * 128 + j] = v.z;
        Wt[(k + 3) * 128 + j] = v.w;
    }
    #pragma unroll
    for (int i = 0; i < 16; i++) {
        int fidx = i * 256 + tid;
        int r = fidx & 127;
        int k = (fidx >> 7) << 2;
        int row = row0 + r;
        float4 v = make_float4(0.f, 0.f, 0.f, 0.f);
        if (row < n) v = __ldg((const float4*)(A + (size_t)row * DD + k));
        As[(k + 0) * 128 + r] = v.x;
        As[(k + 1) * 128 + r] = v.y;
        As[(k + 2) * 128 + r] = v.z;
        As[(k + 3) * 128 + r] = v.w;
    }
    __syncthreads();

    int tx = tid & 15;
    int ty = tid >> 4;

    u64 acc2[4][8];
    #pragma unroll
    for (int p = 0; p < 4; p++)
        #pragma unroll
        for (int c = 0; c < 8; c++) acc2[p][c] = 0ull;

    #pragma unroll 4
    for (int k = 0; k < 128; k++) {
        float4 w0 = *(const float4*)(Wt + k * 128 + tx * 4);
        float4 w1 = *(const float4*)(Wt + k * 128 + 64 + tx * 4);
        u64 wp[8];
        wp[0] = dup2(w0.x); wp[1] = dup2(w0.y); wp[2] = dup2(w0.z); wp[3] = dup2(w0.w);
        wp[4] = dup2(w1.x); wp[5] = dup2(w1.y); wp[6] = dup2(w1.z); wp[7] = dup2(w1.w);
        ulonglong2 q0 = *(const ulonglong2*)(As + k * 128 + ty * 8);
        ulonglong2 q1 = *(const ulonglong2*)(As + k * 128 + ty * 8 + 4);
        u64 pr[4] = {q0.x, q0.y, q1.x, q1.y};
        #pragma unroll
        for (int p = 0; p < 4; p++) {
            #pragma unroll
            for (int c = 0; c < 8; c++) fma2(acc2[p][c], pr[p], wp[c]);
        }
    }

    float4 bv0 = make_float4(0.f, 0.f, 0.f, 0.f), bv1 = bv0;
    if (PHASE == 0) {
        bv0 = __ldg((const float4*)(bias + tx * 4));
        bv1 = __ldg((const float4*)(bias + 64 + tx * 4));
    }
    #pragma unroll
    for (int p = 0; p < 4; p++) {
        float lo[8], hi[8];
        #pragma unroll
        for (int c = 0; c < 8; c++) unpk(lo[c], hi[c], acc2[p][c]);
        #pragma unroll
        for (int half = 0; half < 2; half++) {
            int rr = row0 + ty * 8 + 2 * p + half;
            if (rr >= n) continue;
            float* src = half ? hi : lo;
            float4 o0, o1;
            if (PHASE == 0) {
                o0 = make_float4(src[0] + bv0.x, src[1] + bv0.y, src[2] + bv0.z, src[3] + bv0.w);
                o1 = make_float4(src[4] + bv1.x, src[5] + bv1.y, src[6] + bv1.z, src[7] + bv1.w);
            } else {
                float4 p0 = *(const float4*)(out + (size_t)rr * DD + tx * 4);
                float4 p1 = *(const float4*)(out + (size_t)rr * DD + 64 + tx * 4);
                o0 = make_float4(src[0] + p0.x, src[1] + p0.y, src[2] + p0.z, src[3] + p0.w);
                o1 = make_float4(src[4] + p1.x, src[5] + p1.y, src[6] + p1.z, src[7] + p1.w);
                if (relu) {
                    o0.x = fmaxf(o0.x, 0.f); o0.y = fmaxf(o0.y, 0.f);
                    o0.z = fmaxf(o0.z, 0.f); o0.w = fmaxf(o0.w, 0.f);
                    o1.x = fmaxf(o1.x, 0.f); o1.y = fmaxf(o1.y, 0.f);
                    o1.z = fmaxf(o1.z, 0.f); o1.w = fmaxf(o1.w, 0.f);
                }
            }
            *(float4*)(out + (size_t)rr * DD + tx * 4)      = o0;
            *(float4*)(out + (size_t)rr * DD + 64 + tx * 4) = o1;
            if (PHASE == 1 && h16out) {
                __half2 a0 = __floats2half2_rn(o0.x, o0.y);
                __half2 b0 = __floats2half2_rn(o0.z, o0.w);
                __half2 a1 = __floats2half2_rn(o1.x, o1.y);
                __half2 b1 = __floats2half2_rn(o1.z, o1.w);
                *(uint2*)(h16out + (size_t)rr * DD + tx * 4) =
                    make_uint2(*(uint32_t*)&a0, *(uint32_t*)&b0);
                *(uint2*)(h16out + (size_t)rr * DD + 64 + tx * 4) =
                    make_uint2(*(uint32_t*)&a1, *(uint32_t*)&b1);
            }
        }
    }
}

__global__ void __launch_bounds__(256, 1)
hgemm_kernel(const float* __restrict__ h, const float* __restrict__ Wr,
             const float* __restrict__ bias, float* __restrict__ outp, int n) {
    gemm_body<0>(h, Wr, bias, outp, (__half*)0, n, 0);
}

__global__ void __launch_bounds__(256, 1)
mgemm_kernel(const float* __restrict__ mean, const float* __restrict__ Wl,
             float* __restrict__ out, __half* __restrict__ h16out, int n, int relu) {
    gemm_body<1>(mean, Wl, (const float*)0, out, h16out, n, relu);
}

// ==================== launch ====================
extern "C" void kernel_launch(void* const* d_in, const int* in_sizes, int n_in,
                              void* d_out, int out_size) {
    const float* x   = (const float*)d_in[0];
    const int*   ei  = (const int*)d_in[1];     // int32
    const float* W1l = (const float*)d_in[2];
    const float* W1r = (const float*)d_in[3];
    const float* W2l = (const float*)d_in[4];
    const float* W2r = (const float*)d_in[5];
    const float* W3l = (const float*)d_in[6];
    const float* W3r = (const float*)d_in[7];
    const float* b1  = (const float*)d_in[8];
    const float* b2  = (const float*)d_in[9];
    const float* b3  = (const float*)d_in[10];
    float* out = (float*)d_out;

    int n = in_sizes[0] / DD;
    long long E = (long long)in_sizes[1] / 2;

    float *agg, *h0, *h1;
    __half* h16;
    int *cnt, *cur, *incl, *bsum, *rowptr, *csr;
    cudaGetSymbolAddress((void**)&agg,    g_agg);
    cudaGetSymbolAddress((void**)&h0,     g_h0);
    cudaGetSymbolAddress((void**)&h1,     g_h1);
    cudaGetSymbolAddress((void**)&h16,    g_h16);
    cudaGetSymbolAddress((void**)&cnt,    g_cnt);
    cudaGetSymbolAddress((void**)&cur,    g_cur);
    cudaGetSymbolAddress((void**)&incl,   g_incl);
    cudaGetSymbolAddress((void**)&bsum,   g_bsum);
    cudaGetSymbolAddress((void**)&rowptr, g_rowptr);
    cudaGetSymbolAddress((void**)&csr,    g_csr);

    cudaFuncSetAttribute(hgemm_kernel, cudaFuncAttributeMaxDynamicSharedMemorySize,
                         (int)GEMM_SMEM);
    cudaFuncSetAttribute(mgemm_kernel, cudaFuncAttributeMaxDynamicSharedMemorySize,
                         (int)GEMM_SMEM);

    unsigned eblocks = (unsigned)((E + 255) / 256);
    int total4 = n * DD / 4;
    int nb = (n + SB - 1) / SB;
    int agg_blocks  = (n + 7) / 8;
    int gemm_blocks = (n + 127) / 128;

    // side stream + fork/join events (host objects; legal during capture)
    cudaStream_t s2;
    cudaStreamCreateWithFlags(&s2, cudaStreamNonBlocking);
    cudaEvent_t evF[3], evJ[3];
    for (int i = 0; i < 3; i++) {
        cudaEventCreateWithFlags(&evF[i], cudaEventDisableTiming);
        cudaEventCreateWithFlags(&evJ[i], cudaEventDisableTiming);
    }

    conv16z_kernel<<<(total4 + 255) / 256, 256>>>(x, h16, cnt, cur, total4, n);
    deg_kernel<<<eblocks, 256>>>(ei + E, cnt, E);
    scan1<<<nb, SB>>>(cnt, incl, bsum, n);
    scan2<<<1, 512>>>(bsum, nb);
    scan3<<<(n + 255) / 256, 256>>>(incl, cnt, bsum, rowptr, n, (int)E);
    place_kernel<<<eblocks, 256>>>(ei, rowptr, cur, csr, E);

    const float* hin[3]  = {x,  h0, h1};
    float*       hout[3] = {h0, h1, out};
    const float* Wls[3]  = {W1l, W2l, W3l};
    const float* Wrs[3]  = {W1r, W2r, W3r};
    const float* bs[3]   = {b1, b2, b3};

    for (int L = 0; L < 3; L++) {
        // fork: hgemm (independent of agg) on s2
        cudaEventRecord(evF[L], 0);
        cudaStreamWaitEvent(s2, evF[L], 0);
        hgemm_kernel<<<gemm_blocks, 256, GEMM_SMEM, s2>>>(hin[L], Wrs[L], bs[L], hout[L], n);
        cudaEventRecord(evJ[L], s2);
        // concurrent: agg on main stream
        agg_kernel<<<agg_blocks, 256>>>(h16, rowptr, csr, agg, n);
        // join, then combine
        cudaStreamWaitEvent(0, evJ[L], 0);
        mgemm_kernel<<<gemm_blocks, 256, GEMM_SMEM>>>(agg, Wls[L], hout[L],
                                                      (L < 2) ? h16 : (__half*)0, n, (L < 2) ? 1 : 0);
    }

    for (int i = 0; i < 3; i++) { cudaEventDestroy(evF[i]); cudaEventDestroy(evJ[i]); }
    cudaStreamDestroy(s2);
}

// round 12
// speedup vs baseline: 1.0834x; 1.0834x over previous
#include <cuda_runtime.h>
#include <cuda_fp16.h>
#include <stdint.h>

#define DD 128
#define NMAX 100000
#define EMAX 3200000
typedef unsigned long long u64;

// -------- device-global scratch --------
__device__ float  g_agg[(size_t)NMAX * DD];
__device__ float  g_h0 [(size_t)NMAX * DD];
__device__ float  g_h1 [(size_t)NMAX * DD];
__device__ __half g_h16[(size_t)NMAX * DD];
__device__ int    g_cnt [NMAX];
__device__ int    g_cur [NMAX];
__device__ int    g_incl[NMAX];
__device__ int    g_bsum[512];
__device__ int    g_rowptr[NMAX + 1];
__device__ int    g_csr [EMAX];

// ==================== zero counters ====================
__global__ void zero_kernel(int* __restrict__ cnt, int* __restrict__ cur, int n) {
    int i = blockIdx.x * blockDim.x + threadIdx.x;
    if (i < n) { cnt[i] = 0; cur[i] = 0; }
}

// ==================== fp32 -> fp16 mirror of x ====================
__global__ void conv16_kernel(const float* __restrict__ src, __half* __restrict__ dst,
                              int total4) {
    int i = blockIdx.x * blockDim.x + threadIdx.x;
    if (i < total4) {
        float4 v = __ldcs((const float4*)src + i);     // streaming read
        __half2 a = __floats2half2_rn(v.x, v.y);
        __half2 b = __floats2half2_rn(v.z, v.w);
        *((uint2*)dst + i) = make_uint2(*(uint32_t*)&a, *(uint32_t*)&b);
    }
}

// ==================== CSR build ====================
__global__ void deg_kernel(const int* __restrict__ dst, int* __restrict__ cnt, long long E) {
    long long e = (long long)blockIdx.x * blockDim.x + threadIdx.x;
    if (e < E) atomicAdd(&cnt[dst[e]], 1);
}

#define SB 256
__global__ void scan1(const int* __restrict__ cnt, int* __restrict__ incl,
                      int* __restrict__ bsum, int n) {
    __shared__ int sm[SB];
    int i = blockIdx.x * SB + threadIdx.x;
    int v = (i < n) ? cnt[i] : 0;
    sm[threadIdx.x] = v;
    __syncthreads();
    for (int off = 1; off < SB; off <<= 1) {
        int t = (threadIdx.x >= off) ? sm[threadIdx.x - off] : 0;
        __syncthreads();
        sm[threadIdx.x] += t;
        __syncthreads();
    }
    if (i < n) incl[i] = sm[threadIdx.x];
    if (threadIdx.x == SB - 1) bsum[blockIdx.x] = sm[SB - 1];
}

__global__ void scan2(int* __restrict__ bsum, int nb) {
    __shared__ int sm[512];
    int v = ((int)threadIdx.x < nb) ? bsum[threadIdx.x] : 0;
    sm[threadIdx.x] = v;
    __syncthreads();
    for (int off = 1; off < 512; off <<= 1) {
        int t = (threadIdx.x >= off) ? sm[threadIdx.x - off] : 0;
        __syncthreads();
        sm[threadIdx.x] += t;
        __syncthreads();
    }
    if ((int)threadIdx.x < nb) bsum[threadIdx.x] = sm[threadIdx.x] - v;
}

__global__ void scan3(const int* __restrict__ incl, const int* __restrict__ cnt,
                      const int* __restrict__ bsum, int* __restrict__ rowptr,
                      int n, int E) {
    int i = blockIdx.x * 256 + threadIdx.x;
    if (i < n) rowptr[i] = incl[i] - cnt[i] + bsum[i / SB];
    if (i == 0) rowptr[n] = E;
}

__global__ void place_kernel(const int* __restrict__ ei, const int* __restrict__ rowptr,
                             int* __restrict__ cur, int* __restrict__ csr, long long E) {
    long long e = (long long)blockIdx.x * blockDim.x + threadIdx.x;
    if (e < E) {
        int s = ei[e];
        int d = ei[E + e];
        int pos = rowptr[d] + atomicAdd(&cur[d], 1);
        csr[pos] = s;
    }
}

// ==================== mean aggregation (R10 form, streaming output) ====================
__global__ void agg_kernel(const __half* __restrict__ h16, const int* __restrict__ rowptr,
                           const int* __restrict__ csr, float* __restrict__ agg, int n) {
    int d = blockIdx.x * (blockDim.x >> 5) + (threadIdx.x >> 5);
    int lane = threadIdx.x & 31;
    if (d >= n) return;
    int beg = __ldg(&rowptr[d]);
    int end = __ldg(&rowptr[d + 1]);
    int half = lane >> 4;
    int hl   = lane & 15;

    float acc[8];
    #pragma unroll
    for (int q = 0; q < 8; q++) acc[q] = 0.f;

    for (int j = beg; j < end; j += 32) {
        int cnt = min(32, end - j);
        int s = (lane < cnt) ? __ldg(&csr[j + lane]) : 0;
        int npair = cnt >> 1;
        #pragma unroll 4
        for (int t = 0; t < npair; t++) {
            int ss = __shfl_sync(0xffffffffu, s, 2 * t + half);
            uint4 raw = __ldg((const uint4*)(h16 + (size_t)ss * DD) + hl);
            const __half2* hp = (const __half2*)&raw;
            #pragma unroll
            for (int q = 0; q < 4; q++) {
                float2 f = __half22float2(hp[q]);
                acc[2 * q]     += f.x;
                acc[2 * q + 1] += f.y;
            }
        }
        if (cnt & 1) {
            int ss = __shfl_sync(0xffffffffu, s, cnt - 1);
            if (half == 0) {
                uint4 raw = __ldg((const uint4*)(h16 + (size_t)ss * DD) + hl);
                const __half2* hp = (const __half2*)&raw;
                #pragma unroll
                for (int q = 0; q < 4; q++) {
                    float2 f = __half22float2(hp[q]);
                    acc[2 * q]     += f.x;
                    acc[2 * q + 1] += f.y;
                }
            }
        }
    }
    #pragma unroll
    for (int q = 0; q < 8; q++) acc[q] += __shfl_xor_sync(0xffffffffu, acc[q], 16);

    if (half == 0) {
        float inv = 1.0f / fmaxf((float)(end - beg), 1.0f);
        float4 v0 = make_float4(acc[0] * inv, acc[1] * inv, acc[2] * inv, acc[3] * inv);
        float4 v1 = make_float4(acc[4] * inv, acc[5] * inv, acc[6] * inv, acc[7] * inv);
        float4* dst = (float4*)(agg + (size_t)d * DD + hl * 8);
        __stcs(dst,     v0);     // evict-first: single-use until gemm reads it
        __stcs(dst + 1, v1);
    }
}

// ==================== f32x2 helpers ====================
__device__ __forceinline__ void fma2(u64& d, u64 a, u64 b) {
    asm("fma.rn.f32x2 %0, %1, %2, %0;" : "+l"(d) : "l"(a), "l"(b));
}
__device__ __forceinline__ u64 dup2(float x) {
    u64 r;
    asm("mov.b64 %0, {%1, %1};" : "=l"(r) : "r"(__float_as_uint(x)));
    return r;
}
__device__ __forceinline__ void unpk(float& lo, float& hi, u64 v) {
    unsigned a, b;
    asm("mov.b64 {%0, %1}, %2;" : "=r"(a), "=r"(b) : "l"(v));
    lo = __uint_as_float(a); hi = __uint_as_float(b);
}

// ==================== fused SAGE GEMM (R10 form, streaming A/out) ====================
#define GEMM_SMEM ((256 * 128 + 128 * 128) * sizeof(float))   // 192KB

__global__ void __launch_bounds__(256, 1)
sage_gemm(const float* __restrict__ mean, const float* __restrict__ h,
          const float* __restrict__ Wl, const float* __restrict__ Wr,
          const float* __restrict__ bias, float* __restrict__ out,
          __half* __restrict__ h16out, int n, int relu) {
    extern __shared__ float sm[];
    float* Wt = sm;                 // [256][128]
    float* As = sm + 256 * 128;     // [128][128]

    int tid = threadIdx.x;
    int row0 = blockIdx.x * 128;

    #pragma unroll
    for (int i = 0; i < 32; i++) {
        int fidx = i * 256 + tid;
        int j  = fidx & 127;
        int kk = (fidx >> 7) << 2;
        float4 v;
        if (kk < 128) v = __ldg((const float4*)(Wl + j * DD + kk));
        else          v = __ldg((const float4*)(Wr + j * DD + (kk - 128)));
        Wt[(kk + 0) * 128 + j] = v.x;
        Wt[(kk + 1) * 128 + j] = v.y;
        Wt[(kk + 2) * 128 + j] = v.z;
        Wt[(kk + 3) * 128 + j] = v.w;
    }

    int tx = tid & 15;
    int ty = tid >> 4;

    u64 acc2[4][8];
    #pragma unroll
    for (int p = 0; p < 4; p++)
        #pragma unroll
        for (int c = 0; c < 8; c++) acc2[p][c] = 0ull;

    #pragma unroll
    for (int pass = 0; pass < 2; pass++) {
        const float* A = pass ? h : mean;
        __syncthreads();
        #pragma unroll
        for (int i = 0; i < 16; i++) {
            int fidx = i * 256 + tid;
            int r = fidx & 127;
            int k = (fidx >> 7) << 2;
            int row = row0 + r;
            float4 v = make_float4(0.f, 0.f, 0.f, 0.f);
            if (row < n) v = __ldcs((const float4*)(A + (size_t)row * DD + k));  // streaming
            As[(k + 0) * 128 + r] = v.x;
            As[(k + 1) * 128 + r] = v.y;
            As[(k + 2) * 128 + r] = v.z;
            As[(k + 3) * 128 + r] = v.w;
        }
        __syncthreads();

        const float* WtP = Wt + pass * 128 * 128;
        #pragma unroll 4
        for (int k = 0; k < 128; k++) {
            float4 w0 = *(const float4*)(WtP + k * 128 + tx * 4);
            float4 w1 = *(const float4*)(WtP + k * 128 + 64 + tx * 4);
            u64 wp[8];
            wp[0] = dup2(w0.x); wp[1] = dup2(w0.y); wp[2] = dup2(w0.z); wp[3] = dup2(w0.w);
            wp[4] = dup2(w1.x); wp[5] = dup2(w1.y); wp[6] = dup2(w1.z); wp[7] = dup2(w1.w);
            ulonglong2 q0 = *(const ulonglong2*)(As + k * 128 + ty * 8);
            ulonglong2 q1 = *(const ulonglong2*)(As + k * 128 + ty * 8 + 4);
            u64 pr[4] = {q0.x, q0.y, q1.x, q1.y};
            #pragma unroll
            for (int p = 0; p < 4; p++) {
                #pragma unroll
                for (int c = 0; c < 8; c++) fma2(acc2[p][c], pr[p], wp[c]);
            }
        }
    }

    float4 bv0 = __ldg((const float4*)(bias + tx * 4));
    float4 bv1 = __ldg((const float4*)(bias + 64 + tx * 4));
    #pragma unroll
    for (int p = 0; p < 4; p++) {
        float lo[8], hi[8];
        #pragma unroll
        for (int c = 0; c < 8; c++) unpk(lo[c], hi[c], acc2[p][c]);
        #pragma unroll
        for (int half = 0; half < 2; half++) {
            int rr = row0 + ty * 8 + 2 * p + half;
            if (rr >= n) continue;
            float* src = half ? hi : lo;
            float4 o0 = make_float4(src[0] + bv0.x, src[1] + bv0.y, src[2] + bv0.z, src[3] + bv0.w);
            float4 o1 = make_float4(src[4] + bv1.x, src[5] + bv1.y, src[6] + bv1.z, src[7] + bv1.w);
            if (relu) {
                o0.x = fmaxf(o0.x, 0.f); o0.y = fmaxf(o0.y, 0.f);
                o0.z = fmaxf(o0.z, 0.f); o0.w = fmaxf(o0.w, 0.f);
                o1.x = fmaxf(o1.x, 0.f); o1.y = fmaxf(o1.y, 0.f);
                o1.z = fmaxf(o1.z, 0.f); o1.w = fmaxf(o1.w, 0.f);
            }
            __stcs((float4*)(out + (size_t)rr * DD + tx * 4),      o0);  // streaming
            __stcs((float4*)(out + (size_t)rr * DD + 64 + tx * 4), o1);
            if (h16out) {   // default policy: keep h16 resident in L2
                __half2 a0 = __floats2half2_rn(o0.x, o0.y);
                __half2 b0 = __floats2half2_rn(o0.z, o0.w);
                __half2 a1 = __floats2half2_rn(o1.x, o1.y);
                __half2 b1 = __floats2half2_rn(o1.z, o1.w);
                *(uint2*)(h16out + (size_t)rr * DD + tx * 4) =
                    make_uint2(*(uint32_t*)&a0, *(uint32_t*)&b0);
                *(uint2*)(h16out + (size_t)rr * DD + 64 + tx * 4) =
                    make_uint2(*(uint32_t*)&a1, *(uint32_t*)&b1);
            }
        }
    }
}

// ==================== launch ====================
extern "C" void kernel_launch(void* const* d_in, const int* in_sizes, int n_in,
                              void* d_out, int out_size) {
    const float* x   = (const float*)d_in[0];
    const int*   ei  = (const int*)d_in[1];     // int32
    const float* W1l = (const float*)d_in[2];
    const float* W1r = (const float*)d_in[3];
    const float* W2l = (const float*)d_in[4];
    const float* W2r = (const float*)d_in[5];
    const float* W3l = (const float*)d_in[6];
    const float* W3r = (const float*)d_in[7];
    const float* b1  = (const float*)d_in[8];
    const float* b2  = (const float*)d_in[9];
    const float* b3  = (const float*)d_in[10];
    float* out = (float*)d_out;

    int n = in_sizes[0] / DD;
    long long E = (long long)in_sizes[1] / 2;

    float *agg, *h0, *h1;
    __half* h16;
    int *cnt, *cur, *incl, *bsum, *rowptr, *csr;
    cudaGetSymbolAddress((void**)&agg,    g_agg);
    cudaGetSymbolAddress((void**)&h0,     g_h0);
    cudaGetSymbolAddress((void**)&h1,     g_h1);
    cudaGetSymbolAddress((void**)&h16,    g_h16);
    cudaGetSymbolAddress((void**)&cnt,    g_cnt);
    cudaGetSymbolAddress((void**)&cur,    g_cur);
    cudaGetSymbolAddress((void**)&incl,   g_incl);
    cudaGetSymbolAddress((void**)&bsum,   g_bsum);
    cudaGetSymbolAddress((void**)&rowptr, g_rowptr);
    cudaGetSymbolAddress((void**)&csr,    g_csr);

    cudaFuncSetAttribute(sage_gemm, cudaFuncAttributeMaxDynamicSharedMemorySize,
                         (int)GEMM_SMEM);

    unsigned eblocks = (unsigned)((E + 255) / 256);
    int total4 = n * DD / 4;
    int nb = (n + SB - 1) / SB;
    int agg_blocks  = (n + 7) / 8;
    int gemm_blocks = (n + 127) / 128;

    // side stream: conv16 overlaps the CSR build (disjoint data)
    cudaStream_t s2;
    cudaStreamCreateWithFlags(&s2, cudaStreamNonBlocking);
    cudaEvent_t evF, evJ;
    cudaEventCreateWithFlags(&evF, cudaEventDisableTiming);
    cudaEventCreateWithFlags(&evJ, cudaEventDisableTiming);

    cudaEventRecord(evF, 0);
    cudaStreamWaitEvent(s2, evF, 0);
    conv16_kernel<<<(total4 + 255) / 256, 256, 0, s2>>>(x, h16, total4);
    cudaEventRecord(evJ, s2);

    zero_kernel<<<(n + 255) / 256, 256>>>(cnt, cur, n);
    deg_kernel<<<eblocks, 256>>>(ei + E, cnt, E);
    scan1<<<nb, SB>>>(cnt, incl, bsum, n);
    scan2<<<1, 512>>>(bsum, nb);
    scan3<<<(n + 255) / 256, 256>>>(incl, cnt, bsum, rowptr, n, (int)E);
    place_kernel<<<eblocks, 256>>>(ei, rowptr, cur, csr, E);
    cudaStreamWaitEvent(0, evJ, 0);   // h16 ready before first agg

    // Layer 1
    agg_kernel<<<agg_blocks, 256>>>(h16, rowptr, csr, agg, n);
    sage_gemm<<<gemm_blocks, 256, GEMM_SMEM>>>(agg, x, W1l, W1r, b1, h0, h16, n, 1);
    // Layer 2
    agg_kernel<<<agg_blocks, 256>>>(h16, rowptr, csr, agg, n);
    sage_gemm<<<gemm_blocks, 256, GEMM_SMEM>>>(agg, h0, W2l, W2r, b2, h1, h16, n, 1);
    // Layer 3
    agg_kernel<<<agg_blocks, 256>>>(h16, rowptr, csr, agg, n);
    sage_gemm<<<gemm_blocks, 256, GEMM_SMEM>>>(agg, h1, W3l, W3r, b3, out, (__half*)0, n, 0);

    cudaEventDestroy(evF);
    cudaEventDestroy(evJ);
    cudaStreamDestroy(s2);
}